// round 13
// baseline (speedup 1.0000x reference)
#include <cuda_runtime.h>
#include <cuda_fp16.h>
#include <cstdint>
#include <math_constants.h>

// Shapes (fixed by setup_inputs)
#define B_  32
#define C_  256
#define N_  1024
#define M_  1024

// Recheck thresholds
#define T1 2.0e-2f        // tier-1 commit margin on approx L (covers fp16-S quant)
#define T2 8.0e-3f        // tier-2 commit margin (exact s, approx cb)
#define CAP2 16384

// ---------------------------------------------------------------------------
// Device scratch (allocation-free)
// ---------------------------------------------------------------------------
__device__ __half g_S[(size_t)B_ * N_ * M_];          // 64 MB hh scores (fp16)
__device__ __half g_Qh[N_ * C_];                      // fl16(q/16)  [n][c]
__device__ __half g_Kh[(size_t)B_ * M_ * C_];         // fl16(src) transposed [b][m][c]
__device__ float  g_KT[(size_t)B_ * M_ * C_];         // fp32 src transposed [b][m][c]
__device__ float2 g_cpart[B_][8][M_];                 // per-n-strip col partials
__device__ float  g_cb[B_ * M_];                      // colmax + log(colsum) (approx)
__device__ int    g_idx[B_ * N_];                     // per-row argmax

__device__ int    g_cnt1, g_cnt2;
__device__ int    g_rows1[B_ * N_];
__device__ int    g_rows2[CAP2];
__device__ int    g_k3[CAP2];
__device__ int    g_cand3[CAP2][8];
__device__ float  g_L3[CAP2][8];

// ---------------------------------------------------------------------------
// PTX helpers (sm_80-era: valid on base sm_100 target)
// ---------------------------------------------------------------------------
__device__ __forceinline__ uint32_t smem_u32(const void* p) {
    uint32_t a;
    asm("{ .reg .u64 t; cvta.to.shared.u64 t, %1; cvt.u32.u64 %0, t; }" : "=r"(a) : "l"(p));
    return a;
}
#define CP_ASYNC16(saddr, gaddr) \
    asm volatile("cp.async.cg.shared.global [%0], [%1], 16;" \
                 :: "r"(saddr), "l"(gaddr) : "memory")
#define CP_COMMIT()  asm volatile("cp.async.commit_group;" ::: "memory")
#define CP_WAIT(n)   asm volatile("cp.async.wait_group %0;" :: "n"(n) : "memory")

#define LDMATRIX_X4(r0, r1, r2, r3, addr) \
    asm volatile("ldmatrix.sync.aligned.m8n8.x4.shared.b16 {%0,%1,%2,%3}, [%4];" \
                 : "=r"(r0), "=r"(r1), "=r"(r2), "=r"(r3) : "r"(addr))

__device__ __forceinline__ void mma16816(float* d, const uint32_t* a, const uint32_t* b) {
    asm volatile(
        "mma.sync.aligned.m16n8k16.row.col.f32.f16.f16.f32 "
        "{%0,%1,%2,%3}, {%4,%5,%6,%7}, {%8,%9}, {%0,%1,%2,%3};"
        : "+f"(d[0]), "+f"(d[1]), "+f"(d[2]), "+f"(d[3])
        : "r"(a[0]), "r"(a[1]), "r"(a[2]), "r"(a[3]), "r"(b[0]), "r"(b[1]));
}

__device__ __forceinline__ float warp_fmax(float v) {
    #pragma unroll
    for (int o = 16; o > 0; o >>= 1) v = fmaxf(v, __shfl_xor_sync(0xffffffffu, v, o));
    return v;
}
__device__ __forceinline__ float warp_fsum(float v) {
    #pragma unroll
    for (int o = 16; o > 0; o >>= 1) v += __shfl_xor_sync(0xffffffffu, v, o);
    return v;
}

// ---------------------------------------------------------------------------
// Kernel 0a: Q -> fp16 (temperature folded); also zeroes tier counters.
// ---------------------------------------------------------------------------
__global__ void split_q_kernel(const float* __restrict__ qw) {
    int i = blockIdx.x * 256 + threadIdx.x;
    if (i == 0) { g_cnt1 = 0; g_cnt2 = 0; }
    g_Qh[i] = __float2half(qw[i] * 0.0625f);
}

// ---------------------------------------------------------------------------
// Kernel 0b: src transposed [b][c][m] -> [b][m][c], fp16 (GEMM) + fp32 (tiers)
// ---------------------------------------------------------------------------
__global__ void split_k_kernel(const float* __restrict__ src) {
    __shared__ float tile[32][33];
    int b = blockIdx.z, c0 = blockIdx.y * 32, m0 = blockIdx.x * 32;
    int t = threadIdx.x, tx = t & 31, ty = t >> 5;
    const float* sp = src + (size_t)b * C_ * M_;
    #pragma unroll
    for (int i = 0; i < 4; i++) {
        int c = c0 + ty + i * 8;
        tile[ty + i * 8][tx] = sp[(size_t)c * M_ + m0 + tx];
    }
    __syncthreads();
    #pragma unroll
    for (int i = 0; i < 4; i++) {
        int m = m0 + ty + i * 8;
        float v = tile[tx][ty + i * 8];
        size_t o = ((size_t)b * M_ + m) * C_ + c0 + tx;
        g_Kh[o] = __float2half(v);
        g_KT[o] = v;
    }
}

// ---------------------------------------------------------------------------
// Kernel 1: hh HMMA GEMM, 3-stage cp.async pipeline, ONE sync per k-chunk.
// CTA 128n x 128m, 8 warps (4n x 2m). K: 8 chunks of 32. 48 KB static smem
// (3 stages x 16 KB); epilogue cstats alias stage 0 after pipeline drains.
// ---------------------------------------------------------------------------
#define KC 32
#define NCHUNK 8
#define STAGE_BYTES 16384          // A tile 8 KB + B tile 8 KB

__device__ __forceinline__ uint32_t sw_addr(uint32_t base, int row, int unit) {
    return base + row * 64 + ((unit ^ ((row >> 1) & 3)) << 4);
}

__global__ __launch_bounds__(256, 2)
void gemm_hh_kernel() {
    __shared__ __align__(16) char sstg[3][STAGE_BYTES];
    const uint32_t sb0 = smem_u32(sstg[0]);

    int tid = threadIdx.x;
    int wid = tid >> 5, lid = tid & 31;
    int wn = wid >> 1, wm = wid & 1;

    int m0 = blockIdx.x * 128;
    int n0 = blockIdx.y * 128;
    int b  = blockIdx.z;

    const __half* gA = g_Qh + (size_t)n0 * C_;
    const __half* gB = g_Kh + ((size_t)b * M_ + m0) * C_;

    auto load_chunk = [&](int buf, int kc) {
        uint32_t sbase = sb0 + buf * STAGE_BYTES;
        #pragma unroll
        for (int t = 0; t < 4; t++) {
            int idx  = tid + t * 256;
            int row  = (idx >> 2) & 127;
            int u    = idx & 3;
            if (idx < 512)
                CP_ASYNC16(sw_addr(sbase, row, u), gA + (size_t)row * C_ + kc + u * 8);
            else
                CP_ASYNC16(sw_addr(sbase + 8192, row, u), gB + (size_t)row * C_ + kc + u * 8);
        }
        CP_COMMIT();
    };

    float acc[2][8][4];
    #pragma unroll
    for (int i = 0; i < 2; i++)
        #pragma unroll
        for (int j = 0; j < 8; j++)
            #pragma unroll
            for (int c = 0; c < 4; c++) acc[i][j][c] = 0.0f;

    load_chunk(0, 0);
    load_chunk(1, KC);

    int buf = 0;
    for (int it = 0; it < NCHUNK; it++) {
        if (it + 1 < NCHUNK) { CP_WAIT(1); } else { CP_WAIT(0); }
        __syncthreads();
        if (it + 2 < NCHUNK) {
            int nb = buf + 2; if (nb >= 3) nb -= 3;
            load_chunk(nb, (it + 2) * KC);
        }

        uint32_t Ab = sb0 + buf * STAGE_BYTES;
        uint32_t Bb = Ab + 8192;
        int tile = lid >> 3, trow = lid & 7;

        #pragma unroll
        for (int ks = 0; ks < 2; ks++) {
            uint32_t aF[2][4];
            #pragma unroll
            for (int i = 0; i < 2; i++) {
                int row  = wn * 32 + i * 16 + (tile & 1) * 8 + trow;
                int unit = 2 * ks + (tile >> 1);
                LDMATRIX_X4(aF[i][0], aF[i][1], aF[i][2], aF[i][3],
                            sw_addr(Ab, row, unit));
            }
            uint32_t bF[8][2];
            #pragma unroll
            for (int p = 0; p < 4; p++) {
                int row  = wm * 64 + p * 16 + (tile >> 1) * 8 + trow;
                int unit = 2 * ks + (tile & 1);
                uint32_t r0, r1, r2, r3;
                LDMATRIX_X4(r0, r1, r2, r3, sw_addr(Bb, row, unit));
                bF[2 * p][0] = r0;     bF[2 * p][1] = r1;
                bF[2 * p + 1][0] = r2; bF[2 * p + 1][1] = r3;
            }
            #pragma unroll
            for (int i = 0; i < 2; i++)
                #pragma unroll
                for (int j = 0; j < 8; j++)
                    mma16816(acc[i][j], aF[i], bF[j]);
        }
        if (++buf == 3) buf = 0;
    }

    // Epilogue 1: write S~ as fp16
    int r_in = lid >> 2, c_in = (lid & 3) * 2;
    #pragma unroll
    for (int i = 0; i < 2; i++) {
        #pragma unroll
        for (int j = 0; j < 8; j++) {
            int gr = n0 + wn * 32 + i * 16 + r_in;
            int gc = m0 + wm * 64 + j * 8 + c_in;
            __half2 lo = __floats2half2_rn(acc[i][j][0], acc[i][j][1]);
            __half2 hi = __floats2half2_rn(acc[i][j][2], acc[i][j][3]);
            *(__half2*)(g_S + ((size_t)b * N_ + gr) * M_ + gc) = lo;
            *(__half2*)(g_S + ((size_t)b * N_ + gr + 8) * M_ + gc) = hi;
        }
    }

    // Epilogue 2: column max + sumexp partials (fp32 acc — unquantized).
    // cstats alias stage 0 (pipeline fully drained: WAIT(0) + sync at last iter;
    // last two compute chunks used stages 1 and 2... chunk7 uses buf (7%3)=1,
    // chunk6 used buf 0 but finished before iter-7's barrier).
    float2 (*cstats)[128] = (float2 (*)[128])sstg[0];
    #pragma unroll
    for (int j = 0; j < 8; j++) {
        #pragma unroll
        for (int o = 0; o < 2; o++) {
            float v0 = acc[0][j][o], v1 = acc[0][j][o + 2];
            float v2 = acc[1][j][o], v3 = acc[1][j][o + 2];
            float mx = fmaxf(fmaxf(v0, v1), fmaxf(v2, v3));
            #pragma unroll
            for (int off = 4; off <= 16; off <<= 1)
                mx = fmaxf(mx, __shfl_xor_sync(0xffffffffu, mx, off));
            float sum = __expf(v0 - mx) + __expf(v1 - mx)
                      + __expf(v2 - mx) + __expf(v3 - mx);
            #pragma unroll
            for (int off = 4; off <= 16; off <<= 1)
                sum += __shfl_xor_sync(0xffffffffu, sum, off);
            if (lid < 4)
                cstats[wn][wm * 64 + j * 8 + lid * 2 + o] = make_float2(mx, sum);
        }
    }
    __syncthreads();
    if (tid < 128) {
        float gm = -CUDART_INF_F, gs = 0.0f;
        #pragma unroll
        for (int w = 0; w < 4; w++) {
            float2 p = cstats[w][tid];
            if (p.x > gm) { gs = gs * __expf(gm - p.x) + p.y; gm = p.x; }
            else          { gs += p.y * __expf(p.x - gm); }
        }
        g_cpart[b][blockIdx.y][m0 + tid] = make_float2(gm, gs);
    }
}

// ---------------------------------------------------------------------------
// Kernel 2: combine 8 n-strip partials -> cb~[b][m]
// ---------------------------------------------------------------------------
__global__ void reduce_cb_kernel() {
    int b = blockIdx.y;
    int m = blockIdx.x * 256 + threadIdx.x;
    float gm = -CUDART_INF_F, gs = 0.0f;
    #pragma unroll
    for (int s = 0; s < 8; s++) {
        float2 p = g_cpart[b][s][m];
        if (p.x > gm) { gs = gs * __expf(gm - p.x) + p.y; gm = p.x; }
        else          { gs += p.y * __expf(p.x - gm); }
    }
    g_cb[b * M_ + m] = gm + logf(gs);
}

// ---------------------------------------------------------------------------
// Kernel 3 (tier 1): per-row top-2 of L~ = 2*S~ - cb~ (vectorized).
// Commit if margin > T1, else flag.
// ---------------------------------------------------------------------------
__global__ void rowargmax2_kernel() {
    int row  = blockIdx.x * 8 + (threadIdx.x >> 5);
    int lane = threadIdx.x & 31;
    int b    = row >> 10;
    const uint4*  Sp  = (const uint4*)(g_S + (size_t)row * M_);
    const float4* cbp = (const float4*)(g_cb + b * M_);

    float b1 = -CUDART_INF_F, b2 = -CUDART_INF_F; int i1 = 0;
    #pragma unroll
    for (int q = lane; q < 128; q += 32) {
        uint4 sv = Sp[q];
        float4 ca = cbp[2 * q], cc = cbp[2 * q + 1];
        int m = q * 8;
        float2 f0 = __half22float2(*(__half2*)&sv.x);
        float2 f1 = __half22float2(*(__half2*)&sv.y);
        float2 f2 = __half22float2(*(__half2*)&sv.z);
        float2 f3 = __half22float2(*(__half2*)&sv.w);
        float L[8] = { 2.0f * f0.x - ca.x, 2.0f * f0.y - ca.y,
                       2.0f * f1.x - ca.z, 2.0f * f1.y - ca.w,
                       2.0f * f2.x - cc.x, 2.0f * f2.y - cc.y,
                       2.0f * f3.x - cc.z, 2.0f * f3.y - cc.w };
        #pragma unroll
        for (int k = 0; k < 8; k++) {
            if (L[k] > b1)      { b2 = b1; b1 = L[k]; i1 = m + k; }
            else if (L[k] > b2) { b2 = L[k]; }
        }
    }
    #pragma unroll
    for (int off = 16; off > 0; off >>= 1) {
        float ob1 = __shfl_down_sync(0xffffffffu, b1, off);
        int   oi1 = __shfl_down_sync(0xffffffffu, i1, off);
        float ob2 = __shfl_down_sync(0xffffffffu, b2, off);
        if (ob1 > b1 || (ob1 == b1 && oi1 < i1)) {
            b2 = fmaxf(b1, ob2); b1 = ob1; i1 = oi1;
        } else {
            b2 = fmaxf(b2, ob1);
        }
    }
    if (lane == 0) {
        g_idx[row] = i1;
        if (b1 - b2 <= T1) {
            int s = atomicAdd(&g_cnt1, 1);
            g_rows1[s] = row;
        }
    }
}

// ---------------------------------------------------------------------------
// Kernel 4 (tier 2): ONE WARP per flagged row. Exact fp32 s via COALESCED
// g_KT reads; commit if margin > T2, else push to tier-3 (best in slot 0).
// ---------------------------------------------------------------------------
__global__ __launch_bounds__(256)
void tier2_kernel(const float* __restrict__ qw) {
    __shared__ int s_cand[8][32];
    __shared__ int s_cnt[8];
    int wl = threadIdx.x >> 5, lane = threadIdx.x & 31;
    int gw = blockIdx.x * 8 + wl;
    int nwarp = gridDim.x * 8;
    int cnt1 = g_cnt1;

    for (int f = gw; f < cnt1; f += nwarp) {
        int row = g_rows1[f], b = row >> 10, n = row & 1023;
        const __half* Sp  = g_S + (size_t)row * M_;
        const float*  cbp = g_cb + b * M_;

        float mx = -CUDART_INF_F;
        for (int m = lane; m < M_; m += 32)
            mx = fmaxf(mx, 2.0f * __half2float(Sp[m]) - cbp[m]);
        mx = warp_fmax(mx);

        if (lane == 0) s_cnt[wl] = 0;
        __syncwarp();
        for (int m = lane; m < M_; m += 32) {
            float L = 2.0f * __half2float(Sp[m]) - cbp[m];
            if (L >= mx - T1) {
                int p = atomicAdd(&s_cnt[wl], 1);
                if (p < 32) s_cand[wl][p] = m;
            }
        }
        __syncwarp();
        int K = min(s_cnt[wl], 32);

        float bestL = -CUDART_INF_F, secondL = -CUDART_INF_F;
        int bestM = 1 << 30;
        float myL = -CUDART_INF_F;
        for (int c = 0; c < K; c++) {
            int m = s_cand[wl][c];
            const float* kt = g_KT + ((size_t)b * M_ + m) * C_;
            float s = 0.0f;
            #pragma unroll 4
            for (int cc = lane; cc < C_; cc += 32)
                s += qw[n * C_ + cc] * kt[cc];
            s = warp_fsum(s) * 0.0625f;
            float L = 2.0f * s - cbp[m];
            if (lane == c) myL = L;
            if (L > bestL || (L == bestL && m < bestM)) {
                secondL = bestL; bestL = L; bestM = m;
            } else if (L > secondL) {
                secondL = L;
            }
        }
        if (lane == 0) g_idx[row] = bestM;

        if (bestL - secondL <= T2) {
            int myM = (lane < K) ? s_cand[wl][lane] : -1;
            bool qual = (lane < K) && (bestL - myL <= T2) && (myM != bestM);
            unsigned mask = __ballot_sync(0xffffffffu, qual);
            int nq = __popc(mask);
            int slot = -1;
            if (lane == 0) {
                int s2 = atomicAdd(&g_cnt2, 1);
                slot = (s2 < CAP2) ? s2 : -1;
            }
            slot = __shfl_sync(0xffffffffu, slot, 0);
            if (slot >= 0) {
                if (lane == 0) {
                    g_rows2[slot] = row;
                    g_k3[slot] = min(1 + nq, 8);
                    g_cand3[slot][0] = bestM;
                }
                if (qual) {
                    int rank = 1 + __popc(mask & ((1u << lane) - 1));
                    if (rank < 8) g_cand3[slot][rank] = myM;
                }
            }
        }
    }
}

// ---------------------------------------------------------------------------
// Kernel 5 (tier 3): one BLOCK (1024 thr) per (row, candidate) task.
// Exact fp32 matvec + exact column LSE -> exact L. Coalesced kv via g_KT.
// ---------------------------------------------------------------------------
__global__ __launch_bounds__(1024)
void tier3_kernel(const float* __restrict__ qw) {
    __shared__ float kv[C_];
    __shared__ float wmax[32], wsum[32];
    __shared__ float s_n;
    int t = threadIdx.x, wid = t >> 5, lane = t & 31;
    int ntask = min(g_cnt2, CAP2) * 8;

    for (int task = blockIdx.x; task < ntask; task += gridDim.x) {
        int f = task >> 3, c = task & 7;
        if (c >= g_k3[f]) continue;
        int row = g_rows2[f], b = row >> 10, n = row & 1023;
        int m = g_cand3[f][c];

        if (t < C_) kv[t] = g_KT[((size_t)b * M_ + m) * C_ + t];
        __syncthreads();

        float lmax = -CUDART_INF_F, lsum = 0.0f, sn = 0.0f;
        #pragma unroll 1
        for (int rr = 0; rr < 32; rr++) {
            int r = wid * 32 + rr;
            const float* qp = qw + (size_t)r * C_;
            float s = 0.0f;
            #pragma unroll 4
            for (int cc = lane; cc < C_; cc += 32) s += qp[cc] * kv[cc];
            s = warp_fsum(s) * 0.0625f;
            if (s > lmax) { lsum = lsum * expf(lmax - s) + 1.0f; lmax = s; }
            else          { lsum += expf(s - lmax); }
            if (r == n) sn = s;
        }
        if (lane == 0) {
            wmax[wid] = lmax; wsum[wid] = lsum;
            if ((n >> 5) == wid) s_n = sn;
        }
        __syncthreads();
        if (t == 0) {
            float gm = -CUDART_INF_F, gs = 0.0f;
            for (int w = 0; w < 32; w++) {
                float pm = wmax[w], ps = wsum[w];
                if (pm > gm) { gs = gs * expf(gm - pm) + ps; gm = pm; }
                else         { gs += ps * expf(pm - gm); }
            }
            g_L3[f][c] = 2.0f * s_n - (gm + logf(gs));
        }
        __syncthreads();
    }
}

// ---------------------------------------------------------------------------
// Kernel 6: finalize tier-3 rows (argmax over exact L, lowest-m tie-break)
// ---------------------------------------------------------------------------
__global__ void tier3_finalize_kernel() {
    int f = blockIdx.x * 256 + threadIdx.x;
    int cnt = min(g_cnt2, CAP2);
    if (f >= cnt) return;
    int K3 = g_k3[f];
    float bl = -CUDART_INF_F; int bm = 1 << 30;
    for (int c = 0; c < K3; c++) {
        int m = g_cand3[f][c];
        float L = g_L3[f][c];
        if (L > bl || (L == bl && m < bm)) { bl = L; bm = m; }
    }
    g_idx[g_rows2[f]] = bm;
}

// ---------------------------------------------------------------------------
// Kernel 7: gather.  out[b][c][n] = src[b][c][ idx[b][n] ] (float4 stores)
// ---------------------------------------------------------------------------
__global__ void gather_kernel(const float* __restrict__ src, float* __restrict__ out) {
    __shared__ float row[M_];
    __shared__ int   sidx[N_];
    int b = blockIdx.y, c = blockIdx.x;
    const float* sr = src + ((size_t)b * C_ + c) * M_;
    const int*   ip = g_idx + b * N_;
    float*       op = out + ((size_t)b * C_ + c) * N_;
    int t = threadIdx.x;
    for (int i = t; i < M_; i += blockDim.x) { row[i] = sr[i]; sidx[i] = ip[i]; }
    __syncthreads();
    int i = t * 4;
    if (i < N_) {
        float4 v;
        v.x = row[sidx[i]];     v.y = row[sidx[i + 1]];
        v.z = row[sidx[i + 2]]; v.w = row[sidx[i + 3]];
        *(float4*)&op[i] = v;
    }
}

// ---------------------------------------------------------------------------
extern "C" void kernel_launch(void* const* d_in, const int* in_sizes, int n_in,
                              void* d_out, int out_size) {
    const float* src = (const float*)d_in[0];   // [32,256,32,32]
    const float* qw  = (const float*)d_in[1];   // [1024,256]
    float* out = (float*)d_out;
    (void)in_sizes; (void)n_in; (void)out_size;

    split_q_kernel<<<N_ * C_ / 256, 256>>>(qw);
    split_k_kernel<<<dim3(M_ / 32, C_ / 32, B_), 256>>>(src);

    gemm_hh_kernel<<<dim3(M_ / 128, N_ / 128, B_), 256>>>();

    reduce_cb_kernel<<<dim3(M_ / 256, B_), 256>>>();
    rowargmax2_kernel<<<(B_ * N_) / 8, 256>>>();
    tier2_kernel<<<256, 256>>>(qw);
    tier3_kernel<<<512, 1024>>>(qw);
    tier3_finalize_kernel<<<CAP2 / 256, 256>>>();
    gather_kernel<<<dim3(C_, B_), 256>>>(src, out);
}

// round 15
// speedup vs baseline: 1.5629x; 1.5629x over previous
#include <cuda_runtime.h>
#include <cuda_fp16.h>
#include <cstdint>
#include <math_constants.h>

// Shapes (fixed by setup_inputs)
#define B_  32
#define C_  256
#define N_  1024
#define M_  1024

// ---------------------------------------------------------------------------
// Device scratch (allocation-free)
// ---------------------------------------------------------------------------
__device__ float  g_S[(size_t)B_ * N_ * M_];          // 128 MB scores (fp32, near-exact)
__device__ __half g_Qs[2][N_ * C_];                   // (Q/16) fp16 limbs [n][c]
__device__ __half g_Ks[2][(size_t)B_ * M_ * C_];      // src fp16 limbs, [b][m][c]
__device__ float2 g_cpart[B_][8][M_];                 // per-n-strip col partials
__device__ float  g_cb[B_ * M_];                      // colmax + log(colsum)
__device__ int    g_idx[B_ * N_];                     // per-row argmax

__device__ __forceinline__ void split2(float v, __half& h, __half& m) {
    h = __float2half(v);
    m = __float2half(v - __half2float(h));
}

// ---------------------------------------------------------------------------
// PTX helpers (sm_80-era: valid on base sm_100 target)
// ---------------------------------------------------------------------------
__device__ __forceinline__ uint32_t smem_u32(const void* p) {
    uint32_t a;
    asm("{ .reg .u64 t; cvta.to.shared.u64 t, %1; cvt.u32.u64 %0, t; }" : "=r"(a) : "l"(p));
    return a;
}
#define CP_ASYNC16(saddr, gaddr) \
    asm volatile("cp.async.cg.shared.global [%0], [%1], 16;" \
                 :: "r"(saddr), "l"(gaddr) : "memory")
#define CP_COMMIT()  asm volatile("cp.async.commit_group;" ::: "memory")
#define CP_WAIT(n)   asm volatile("cp.async.wait_group %0;" :: "n"(n) : "memory")

#define LDMATRIX_X4(r0, r1, r2, r3, addr) \
    asm volatile("ldmatrix.sync.aligned.m8n8.x4.shared.b16 {%0,%1,%2,%3}, [%4];" \
                 : "=r"(r0), "=r"(r1), "=r"(r2), "=r"(r3) : "r"(addr))

__device__ __forceinline__ void mma16816(float* d, const uint32_t* a, const uint32_t* b) {
    asm volatile(
        "mma.sync.aligned.m16n8k16.row.col.f32.f16.f16.f32 "
        "{%0,%1,%2,%3}, {%4,%5,%6,%7}, {%8,%9}, {%0,%1,%2,%3};"
        : "+f"(d[0]), "+f"(d[1]), "+f"(d[2]), "+f"(d[3])
        : "r"(a[0]), "r"(a[1]), "r"(a[2]), "r"(a[3]), "r"(b[0]), "r"(b[1]));
}

// ---------------------------------------------------------------------------
// Kernel 0a: split Q (temperature 1/16 folded in)
// ---------------------------------------------------------------------------
__global__ void split_q_kernel(const float* __restrict__ qw) {
    int i = blockIdx.x * 256 + threadIdx.x;
    float v = qw[i] * 0.0625f;
    __half h, m;
    split2(v, h, m);
    g_Qs[0][i] = h; g_Qs[1][i] = m;
}

// ---------------------------------------------------------------------------
// Kernel 0b: split + transpose src [b][c][m] -> [b][m][c]
// ---------------------------------------------------------------------------
__global__ void split_k_kernel(const float* __restrict__ src) {
    __shared__ float tile[32][33];
    int b = blockIdx.z, c0 = blockIdx.y * 32, m0 = blockIdx.x * 32;
    int t = threadIdx.x, tx = t & 31, ty = t >> 5;
    const float* sp = src + (size_t)b * C_ * M_;
    #pragma unroll
    for (int i = 0; i < 4; i++) {
        int c = c0 + ty + i * 8;
        tile[ty + i * 8][tx] = sp[(size_t)c * M_ + m0 + tx];
    }
    __syncthreads();
    #pragma unroll
    for (int i = 0; i < 4; i++) {
        int m = m0 + ty + i * 8;
        float v = tile[tx][ty + i * 8];
        __half h, mm;
        split2(v, h, mm);
        size_t o = ((size_t)b * M_ + m) * C_ + c0 + tx;
        g_Ks[0][o] = h; g_Ks[1][o] = mm;
    }
}

// ---------------------------------------------------------------------------
// Kernel 1: fp16x3 HMMA GEMM at occupancy 2 (round-6 exact mainloop with the
// round-12-validated launch_bounds/static-smem configuration).
//   S[b][n][m] = sum_c (q[n][c]/16)*src[b][c][m]; products hh, hm, mh.
// CTA 128n x 128m, 8 warps (4n x 2m); K: 3 limb segs x 8 chunks of 32,
// double-buffered cp.async; 36 KB static smem, <=128 regs -> 2 CTAs/SM.
// Fused epilogue: per-column (over 128 n-rows) max + sumexp partials.
// ---------------------------------------------------------------------------
#define KC 32
#define NITER 24    // 3 segs * 8 chunks

struct GemmSmem {
    char   A[2][128 * 64];   // 8 KB each
    char   B[2][128 * 64];
    float2 cstats[4][128];
};

__device__ __forceinline__ uint32_t sw_addr(uint32_t base, int row, int unit) {
    return base + row * 64 + ((unit ^ ((row >> 1) & 3)) << 4);
}

__global__ __launch_bounds__(256, 2)
void gemm_fp16x3_kernel() {
    __shared__ GemmSmem sm;
    const uint32_t sbA[2] = { smem_u32(sm.A[0]), smem_u32(sm.A[1]) };
    const uint32_t sbB[2] = { smem_u32(sm.B[0]), smem_u32(sm.B[1]) };

    int tid = threadIdx.x;
    int wid = tid >> 5, lid = tid & 31;
    int wn = wid >> 1, wm = wid & 1;

    int m0 = blockIdx.x * 128;
    int n0 = blockIdx.y * 128;
    int b  = blockIdx.z;

    // limb product table: hh, hm, mh
    const int sa_tab[3] = {0, 0, 1};
    const int sb_tab[3] = {0, 1, 0};

    auto load_chunk = [&](int buf, int it) {
        int seg = it >> 3, kc = (it & 7) * KC;
        const __half* gA = g_Qs[sa_tab[seg]] + (size_t)n0 * C_ + kc;
        const __half* gB = g_Ks[sb_tab[seg]] + ((size_t)b * M_ + m0) * C_ + kc;
        #pragma unroll
        for (int t = 0; t < 4; t++) {
            int idx  = tid + t * 256;
            int row  = (idx >> 2) & 127;
            int u    = idx & 3;
            if (idx < 512)
                CP_ASYNC16(sw_addr(sbA[buf], row, u), gA + (size_t)row * C_ + u * 8);
            else
                CP_ASYNC16(sw_addr(sbB[buf], row, u), gB + (size_t)row * C_ + u * 8);
        }
        CP_COMMIT();
    };

    float acc[2][8][4];
    #pragma unroll
    for (int i = 0; i < 2; i++)
        #pragma unroll
        for (int j = 0; j < 8; j++)
            #pragma unroll
            for (int c = 0; c < 4; c++) acc[i][j][c] = 0.0f;

    load_chunk(0, 0);

    for (int it = 0; it < NITER; it++) {
        __syncthreads();                        // buffer (it+1)&1 free to overwrite
        if (it + 1 < NITER) {
            load_chunk((it + 1) & 1, it + 1);
            CP_WAIT(1);
        } else {
            CP_WAIT(0);
        }
        __syncthreads();                        // chunk `it` visible to all

        uint32_t Ab = sbA[it & 1], Bb = sbB[it & 1];
        int tile = lid >> 3, trow = lid & 7;

        #pragma unroll
        for (int ks = 0; ks < 2; ks++) {
            uint32_t aF[2][4];
            #pragma unroll
            for (int i = 0; i < 2; i++) {
                int row  = wn * 32 + i * 16 + (tile & 1) * 8 + trow;
                int unit = 2 * ks + (tile >> 1);
                LDMATRIX_X4(aF[i][0], aF[i][1], aF[i][2], aF[i][3],
                            sw_addr(Ab, row, unit));
            }
            uint32_t bF[8][2];
            #pragma unroll
            for (int p = 0; p < 4; p++) {
                int row  = wm * 64 + p * 16 + (tile >> 1) * 8 + trow;
                int unit = 2 * ks + (tile & 1);
                uint32_t r0, r1, r2, r3;
                LDMATRIX_X4(r0, r1, r2, r3, sw_addr(Bb, row, unit));
                bF[2 * p][0] = r0;     bF[2 * p][1] = r1;
                bF[2 * p + 1][0] = r2; bF[2 * p + 1][1] = r3;
            }
            #pragma unroll
            for (int i = 0; i < 2; i++)
                #pragma unroll
                for (int j = 0; j < 8; j++)
                    mma16816(acc[i][j], aF[i], bF[j]);
        }
    }

    // Epilogue 1: write S (fp32)
    int r_in = lid >> 2, c_in = (lid & 3) * 2;
    #pragma unroll
    for (int i = 0; i < 2; i++) {
        #pragma unroll
        for (int j = 0; j < 8; j++) {
            int gr = n0 + wn * 32 + i * 16 + r_in;
            int gc = m0 + wm * 64 + j * 8 + c_in;
            float* p0 = g_S + ((size_t)b * N_ + gr) * M_ + gc;
            float* p1 = p0 + 8 * M_;
            *(float2*)p0 = make_float2(acc[i][j][0], acc[i][j][1]);
            *(float2*)p1 = make_float2(acc[i][j][2], acc[i][j][3]);
        }
    }

    // Epilogue 2: column (over n) max + sumexp partials
    #pragma unroll
    for (int j = 0; j < 8; j++) {
        #pragma unroll
        for (int o = 0; o < 2; o++) {
            float v0 = acc[0][j][o], v1 = acc[0][j][o + 2];
            float v2 = acc[1][j][o], v3 = acc[1][j][o + 2];
            float mx = fmaxf(fmaxf(v0, v1), fmaxf(v2, v3));
            #pragma unroll
            for (int off = 4; off <= 16; off <<= 1)
                mx = fmaxf(mx, __shfl_xor_sync(0xffffffffu, mx, off));
            float sum = __expf(v0 - mx) + __expf(v1 - mx)
                      + __expf(v2 - mx) + __expf(v3 - mx);
            #pragma unroll
            for (int off = 4; off <= 16; off <<= 1)
                sum += __shfl_xor_sync(0xffffffffu, sum, off);
            if (lid < 4)
                sm.cstats[wn][wm * 64 + j * 8 + lid * 2 + o] = make_float2(mx, sum);
        }
    }
    __syncthreads();
    if (tid < 128) {
        float gm = -CUDART_INF_F, gs = 0.0f;
        #pragma unroll
        for (int w = 0; w < 4; w++) {
            float2 p = sm.cstats[w][tid];
            if (p.x > gm) { gs = gs * __expf(gm - p.x) + p.y; gm = p.x; }
            else          { gs += p.y * __expf(p.x - gm); }
        }
        g_cpart[b][blockIdx.y][m0 + tid] = make_float2(gm, gs);
    }
}

// ---------------------------------------------------------------------------
// Kernel 2: combine 8 n-strip partials -> cb[b][m] = colmax + log(colsum)
// ---------------------------------------------------------------------------
__global__ void reduce_cb_kernel() {
    int b = blockIdx.y;
    int m = blockIdx.x * 256 + threadIdx.x;
    float gm = -CUDART_INF_F, gs = 0.0f;
    #pragma unroll
    for (int s = 0; s < 8; s++) {
        float2 p = g_cpart[b][s][m];
        if (p.x > gm) { gs = gs * __expf(gm - p.x) + p.y; gm = p.x; }
        else          { gs += p.y * __expf(p.x - gm); }
    }
    g_cb[b * M_ + m] = gm + logf(gs);
}

// ---------------------------------------------------------------------------
// Kernel 3: per-row argmax of  L = 2*S - cb.  One warp per row, float4 loads.
// ---------------------------------------------------------------------------
__global__ void rowargmax_kernel() {
    int row  = blockIdx.x * 8 + (threadIdx.x >> 5);
    int lane = threadIdx.x & 31;
    int b    = row >> 10;
    const float4* Sp = (const float4*)(g_S + (size_t)row * M_);
    const float4* cb = (const float4*)(g_cb + b * M_);

    float best = -CUDART_INF_F; int bi = 0;
    #pragma unroll 2
    for (int q = lane; q < M_ / 4; q += 32) {
        float4 s = Sp[q];
        float4 c = cb[q];
        int m = q * 4;
        float L0 = 2.0f * s.x - c.x;
        float L1 = 2.0f * s.y - c.y;
        float L2 = 2.0f * s.z - c.z;
        float L3 = 2.0f * s.w - c.w;
        if (L0 > best) { best = L0; bi = m; }
        if (L1 > best) { best = L1; bi = m + 1; }
        if (L2 > best) { best = L2; bi = m + 2; }
        if (L3 > best) { best = L3; bi = m + 3; }
    }
    #pragma unroll
    for (int off = 16; off > 0; off >>= 1) {
        float ob = __shfl_down_sync(0xffffffffu, best, off);
        int   oi = __shfl_down_sync(0xffffffffu, bi, off);
        if (ob > best || (ob == best && oi < bi)) { best = ob; bi = oi; }
    }
    if (lane == 0) g_idx[row] = bi;
}

// ---------------------------------------------------------------------------
// Kernel 4: gather.  out[b][c][n] = src[b][c][ idx[b][n] ] (float4 stores)
// ---------------------------------------------------------------------------
__global__ void gather_kernel(const float* __restrict__ src, float* __restrict__ out) {
    __shared__ float row[M_];
    __shared__ int   sidx[N_];
    int b = blockIdx.y, c = blockIdx.x;
    const float* sr = src + ((size_t)b * C_ + c) * M_;
    const int*   ip = g_idx + b * N_;
    float*       op = out + ((size_t)b * C_ + c) * N_;
    int t = threadIdx.x;
    for (int i = t; i < M_; i += blockDim.x) { row[i] = sr[i]; sidx[i] = ip[i]; }
    __syncthreads();
    int i = t * 4;
    if (i < N_) {
        float4 v;
        v.x = row[sidx[i]];     v.y = row[sidx[i + 1]];
        v.z = row[sidx[i + 2]]; v.w = row[sidx[i + 3]];
        *(float4*)&op[i] = v;
    }
}

// ---------------------------------------------------------------------------
extern "C" void kernel_launch(void* const* d_in, const int* in_sizes, int n_in,
                              void* d_out, int out_size) {
    const float* src = (const float*)d_in[0];   // [32,256,32,32]
    const float* qw  = (const float*)d_in[1];   // [1024,256]
    float* out = (float*)d_out;
    (void)in_sizes; (void)n_in; (void)out_size;

    split_q_kernel<<<N_ * C_ / 256, 256>>>(qw);
    split_k_kernel<<<dim3(M_ / 32, C_ / 32, B_), 256>>>(src);

    gemm_fp16x3_kernel<<<dim3(M_ / 128, N_ / 128, B_), 256>>>();

    reduce_cb_kernel<<<dim3(M_ / 256, B_), 256>>>();
    rowargmax_kernel<<<(B_ * N_) / 8, 256>>>();
    gather_kernel<<<dim3(C_, B_), 256>>>(src, out);
}